// round 2
// baseline (speedup 1.0000x reference)
#include <cuda_runtime.h>
#include <math.h>

#define NN 50000
#define NE 600000
#define HH 128
#define EDD 16
#define TDD 32

#define ET 32      // edges per tile
#define EG 16      // edges per thread group
#define PC_NB 8    // nodes per block, precompute
#define PH_NB 16   // nodes per tile, phi_h

static_assert(NE % ET == 0, "tile divides E");

// ---------------- device scratch (no allocations allowed) ----------------
__device__ float g_A1[NN * HH];
__device__ float g_A2[NN * HH];
__device__ float g_B1[NN * HH];
__device__ float g_B2[NN * HH];
__device__ float g_msg[NN * HH];
__device__ float g_coord[NN * 3];
__device__ int   g_is64;

__device__ __forceinline__ float silu_f(float v) {
    return v / (1.f + __expf(-v));
}

// ---------------- int32 vs int64 edge_index detection ----------------
__global__ void detect_kernel(const void* __restrict__ ei) {
    __shared__ int ok;
    if (threadIdx.x == 0) ok = 1;
    __syncthreads();
    const long long* p = (const long long*)ei;
    long long v = p[threadIdx.x];  // 256 samples, well within buffer
    if (v < 0 || v >= NN) atomicExch(&ok, 0);
    __syncthreads();
    if (threadIdx.x == 0) g_is64 = ok;
}

// ---------------- per-node layer-1 partials + accumulator zeroing ----------------
__global__ __launch_bounds__(128)
void precompute_kernel(const float* __restrict__ h, const float* __restrict__ t_emb,
                       const float* __restrict__ We_w1, const float* __restrict__ We_b1,
                       const float* __restrict__ Wx_w1, const float* __restrict__ Wx_b1)
{
    __shared__ float hbuf[PC_NB][HH];
    __shared__ float tbuf[PC_NB][TDD];
    int col = threadIdx.x;
    int n0 = blockIdx.x * PC_NB;

    for (int i = col; i < PC_NB * HH; i += 128) {
        int j = i / HH, k = i % HH;
        int n = n0 + j;
        hbuf[j][k] = (n < NN) ? h[(size_t)n * HH + k] : 0.f;
    }
    for (int i = col; i < PC_NB * TDD; i += 128) {
        int j = i / TDD, k = i % TDD;
        int n = n0 + j;
        tbuf[j][k] = (n < NN) ? t_emb[(size_t)n * TDD + k] : 0.f;
    }
    __syncthreads();

    float a1[PC_NB], a2[PC_NB], b1[PC_NB], b2[PC_NB];
    float be = We_b1[col], bx = Wx_b1[col];
#pragma unroll
    for (int j = 0; j < PC_NB; j++) { a1[j] = be; b1[j] = bx; a2[j] = 0.f; b2[j] = 0.f; }

    for (int k = 0; k < HH; k++) {
        float wa1 = We_w1[(size_t)k * HH + col];
        float wa2 = We_w1[(size_t)(HH + k) * HH + col];
        float wb1 = Wx_w1[(size_t)k * HH + col];
        float wb2 = Wx_w1[(size_t)(HH + k) * HH + col];
#pragma unroll
        for (int j = 0; j < PC_NB; j++) {
            float hv = hbuf[j][k];
            a1[j] = fmaf(hv, wa1, a1[j]);
            a2[j] = fmaf(hv, wa2, a2[j]);
            b1[j] = fmaf(hv, wb1, b1[j]);
            b2[j] = fmaf(hv, wb2, b2[j]);
        }
    }
    for (int k = 0; k < TDD; k++) {
        float wta = We_w1[(size_t)(273 + k) * HH + col];  // t_src rows in We_w1
        float wtb = Wx_w1[(size_t)(272 + k) * HH + col];  // t_src rows in Wx_w1
#pragma unroll
        for (int j = 0; j < PC_NB; j++) {
            float tv = tbuf[j][k];
            a1[j] = fmaf(tv, wta, a1[j]);
            b1[j] = fmaf(tv, wtb, b1[j]);
        }
    }
#pragma unroll
    for (int j = 0; j < PC_NB; j++) {
        int n = n0 + j;
        if (n < NN) {
            size_t o = (size_t)n * HH + col;
            g_A1[o] = a1[j];
            g_A2[o] = a2[j];
            g_B1[o] = b1[j];
            g_B2[o] = b2[j];
            g_msg[o] = 0.f;
        }
    }
    if (col < PC_NB * 3) {
        int n = n0 + col / 3;
        if (n < NN) g_coord[n * 3 + col % 3] = 0.f;
    }
}

// ---------------- edge kernel: persistent, smem-resident weights ----------------
// smem float offsets
#define O_WE2   0
#define O_WX2   (O_WE2 + 128*128)
#define O_WEXTE (O_WX2 + 128*128)      // 17 x 128 : We_w1 rows 256..272 (dist + edge_attr)
#define O_WEXTX (O_WEXTE + 17*128)     // 16 x 128 : Wx_w1 rows 256..271 (edge_attr)
#define O_WEB2  (O_WEXTX + 16*128)
#define O_WXB2  (O_WEB2 + 128)
#define O_WATT  (O_WXB2 + 128)
#define O_WX3   (O_WATT + 128)
#define O_EXT   (O_WX3 + 128)          // 17 x ET transposed [row][edge]
#define O_DIFFN (O_EXT + 17*ET)        // 3 x ET
#define O_SRC   (O_DIFFN + 3*ET)       // ET ints
#define O_DST   (O_SRC + ET)           // ET ints
#define O_M1T   (O_DST + ET)           // 128 x 36 (padded, transposed activations)
#define O_C1T   (O_M1T + 128*36)       // 128 x 36
#define O_RED   (O_C1T + 128*36)       // 2 grp x 4 warp x EG
#define O_CW    (O_RED + 128)          // ET
#define EDGE_SMEM_FLOATS (O_CW + ET)
#define EDGE_SMEM_BYTES  (EDGE_SMEM_FLOATS * 4)

__global__ __launch_bounds__(256, 1)
void edge_kernel(const float* __restrict__ x, const void* __restrict__ ei,
                 const float* __restrict__ edge_attr,
                 const float* __restrict__ We_w2, const float* __restrict__ We_b2,
                 const float* __restrict__ Watt_w, const float* __restrict__ Watt_b,
                 const float* __restrict__ Wx_w2, const float* __restrict__ Wx_b2,
                 const float* __restrict__ Wx_w3,
                 const float* __restrict__ We_w1, const float* __restrict__ Wx_w1)
{
    extern __shared__ float sm[];
    int tid = threadIdx.x;

    for (int i = tid; i < 128 * 128; i += 256) { sm[O_WE2 + i] = We_w2[i]; sm[O_WX2 + i] = Wx_w2[i]; }
    for (int i = tid; i < 17 * 128; i += 256) sm[O_WEXTE + i] = We_w1[256 * 128 + i];
    for (int i = tid; i < 16 * 128; i += 256) sm[O_WEXTX + i] = Wx_w1[256 * 128 + i];
    if (tid < 128) {
        sm[O_WEB2 + tid] = We_b2[tid];
        sm[O_WXB2 + tid] = Wx_b2[tid];
        sm[O_WATT + tid] = Watt_w[tid];
        sm[O_WX3  + tid] = Wx_w3[tid];
    }
    int is64 = g_is64;
    float attb = Watt_b[0];
    const long long* e64 = (const long long*)ei;
    const int*       e32 = (const int*)ei;
    int* sSrc = (int*)(sm + O_SRC);
    int* sDst = (int*)(sm + O_DST);

    int col = tid & 127;
    int grp = tid >> 7;
    int eb = grp * EG;
    int lane = tid & 31;
    int warp4 = (tid >> 5) & 3;

    for (int tile = blockIdx.x; tile < NE / ET; tile += gridDim.x) {
        int e0 = tile * ET;
        __syncthreads();  // protect staging vs previous tile's readers

        // ---- stage per-edge scalars ----
        if (tid < ET) {
            int e = e0 + tid;
            int s, d;
            if (is64) { s = (int)e64[e]; d = (int)e64[NE + e]; }
            else      { s = e32[e];      d = e32[NE + e]; }
            sSrc[tid] = s; sDst[tid] = d;
            float dx = x[s * 3 + 0] - x[d * 3 + 0];
            float dy = x[s * 3 + 1] - x[d * 3 + 1];
            float dz = x[s * 3 + 2] - x[d * 3 + 2];
            float dsq = dx * dx + dy * dy + dz * dz;
            float inv = 1.f / (sqrtf(dsq + 1e-8f) + 1.f);
            sm[O_EXT + 0 * ET + tid]   = dsq;
            sm[O_DIFFN + 0 * ET + tid] = dx * inv;
            sm[O_DIFFN + 1 * ET + tid] = dy * inv;
            sm[O_DIFFN + 2 * ET + tid] = dz * inv;
        }
        for (int i = tid; i < ET * EDD; i += 256) {
            int e = i / EDD, j = i % EDD;
            sm[O_EXT + (1 + j) * ET + e] = edge_attr[(size_t)(e0 + e) * EDD + j];
        }
        __syncthreads();

        // ---- phase A: layer-1 via node partials + K=17 ext GEMM ----
        float u[EG], v[EG];
#pragma unroll
        for (int q = 0; q < EG; q++) {
            int s = sSrc[eb + q], d = sDst[eb + q];
            u[q] = g_A1[(size_t)s * HH + col] + g_A2[(size_t)d * HH + col];
            v[q] = g_B1[(size_t)s * HH + col] + g_B2[(size_t)d * HH + col];
        }
#pragma unroll
        for (int r = 0; r < 17; r++) {
            float we = sm[O_WEXTE + r * 128 + col];
            float wx = (r >= 1) ? sm[O_WEXTX + (r - 1) * 128 + col] : 0.f;
#pragma unroll
            for (int q = 0; q < EG; q++) {
                float ev = sm[O_EXT + r * ET + eb + q];
                u[q] = fmaf(ev, we, u[q]);
                if (r >= 1) v[q] = fmaf(ev, wx, v[q]);
            }
        }
#pragma unroll
        for (int q = 0; q < EG; q++) {
            sm[O_M1T + col * 36 + eb + q] = silu_f(u[q]);
            sm[O_C1T + col * 36 + eb + q] = silu_f(v[q]);
        }
        __syncthreads();

        // ---- phase B: m2 = silu(u) @ We_w2 + b2; attention; msg atomics ----
        float m2[EG];
        {
            float b = sm[O_WEB2 + col];
#pragma unroll
            for (int q = 0; q < EG; q++) m2[q] = b;
        }
        for (int k = 0; k < 128; k++) {
            float w = sm[O_WE2 + k * 128 + col];
            const float4* p = (const float4*)(sm + O_M1T + k * 36 + eb);
#pragma unroll
            for (int q4 = 0; q4 < 4; q4++) {
                float4 a = p[q4];
                m2[q4 * 4 + 0] = fmaf(w, a.x, m2[q4 * 4 + 0]);
                m2[q4 * 4 + 1] = fmaf(w, a.y, m2[q4 * 4 + 1]);
                m2[q4 * 4 + 2] = fmaf(w, a.z, m2[q4 * 4 + 2]);
                m2[q4 * 4 + 3] = fmaf(w, a.w, m2[q4 * 4 + 3]);
            }
        }
        float pa[EG];
        {
            float wA = sm[O_WATT + col];
#pragma unroll
            for (int q = 0; q < EG; q++) pa[q] = m2[q] * wA;
        }
#pragma unroll
        for (int msk = 16; msk > 0; msk >>= 1)
#pragma unroll
            for (int q = 0; q < EG; q++)
                pa[q] += __shfl_xor_sync(0xffffffffu, pa[q], msk);
        if (lane == 0) {
#pragma unroll
            for (int q = 0; q < EG; q++)
                sm[O_RED + (grp * 4 + warp4) * EG + q] = pa[q];
        }
        __syncthreads();
#pragma unroll
        for (int q = 0; q < EG; q++) {
            float s = sm[O_RED + (grp * 4 + 0) * EG + q] + sm[O_RED + (grp * 4 + 1) * EG + q]
                    + sm[O_RED + (grp * 4 + 2) * EG + q] + sm[O_RED + (grp * 4 + 3) * EG + q];
            float att = 1.f / (1.f + __expf(-(s + attb)));
            atomicAdd(&g_msg[(size_t)sDst[eb + q] * HH + col], att * m2[q]);
        }
        __syncthreads();  // sRed reuse barrier

        // ---- phase C: c2 = silu(silu(v) @ Wx_w2 + b); coord weight; coord atomics ----
        float c2[EG];
        {
            float b = sm[O_WXB2 + col];
#pragma unroll
            for (int q = 0; q < EG; q++) c2[q] = b;
        }
        for (int k = 0; k < 128; k++) {
            float w = sm[O_WX2 + k * 128 + col];
            const float4* p = (const float4*)(sm + O_C1T + k * 36 + eb);
#pragma unroll
            for (int q4 = 0; q4 < 4; q4++) {
                float4 a = p[q4];
                c2[q4 * 4 + 0] = fmaf(w, a.x, c2[q4 * 4 + 0]);
                c2[q4 * 4 + 1] = fmaf(w, a.y, c2[q4 * 4 + 1]);
                c2[q4 * 4 + 2] = fmaf(w, a.z, c2[q4 * 4 + 2]);
                c2[q4 * 4 + 3] = fmaf(w, a.w, c2[q4 * 4 + 3]);
            }
        }
        float pc[EG];
        {
            float wC = sm[O_WX3 + col];
#pragma unroll
            for (int q = 0; q < EG; q++) pc[q] = silu_f(c2[q]) * wC;
        }
#pragma unroll
        for (int msk = 16; msk > 0; msk >>= 1)
#pragma unroll
            for (int q = 0; q < EG; q++)
                pc[q] += __shfl_xor_sync(0xffffffffu, pc[q], msk);
        if (lane == 0) {
#pragma unroll
            for (int q = 0; q < EG; q++)
                sm[O_RED + (grp * 4 + warp4) * EG + q] = pc[q];
        }
        __syncthreads();
        if (col < EG) {
            int q = col;
            float s = sm[O_RED + (grp * 4 + 0) * EG + q] + sm[O_RED + (grp * 4 + 1) * EG + q]
                    + sm[O_RED + (grp * 4 + 2) * EG + q] + sm[O_RED + (grp * 4 + 3) * EG + q];
            sm[O_CW + eb + q] = tanhf(s);
        }
        __syncthreads();
        if (tid < 3 * ET) {
            int e = tid & 31, c = tid >> 5;
            float val = sm[O_DIFFN + c * ET + e] * sm[O_CW + e] * 2.5f;
            atomicAdd(&g_coord[(size_t)sDst[e] * 3 + c], val);
        }
    }
}

// ---------------- phi_h + output assembly ----------------
#define NODE_SMEM_FLOATS (256*128 + 128*128 + 128 + 128 + PH_NB*256 + 128*17)
#define NODE_SMEM_BYTES  (NODE_SMEM_FLOATS * 4)

__global__ __launch_bounds__(256, 1)
void node_out_kernel(const float* __restrict__ h, const float* __restrict__ x,
                     const float* __restrict__ Wh_w1, const float* __restrict__ Wh_b1,
                     const float* __restrict__ Wh_w2, const float* __restrict__ Wh_b2,
                     float* __restrict__ out)
{
    extern __shared__ float sm[];
    float* sW1  = sm;                    // 256 x 128
    float* sW2  = sW1 + 256 * 128;       // 128 x 128
    float* sB1  = sW2 + 128 * 128;       // 128
    float* sB2  = sB1 + 128;             // 128
    float* sIn  = sB2 + 128;             // PH_NB x 256
    float* sHid = sIn + PH_NB * 256;     // 128 x 17 (padded transposed hidden)

    int tid = threadIdx.x;
    for (int i = tid; i < 256 * 128; i += 256) sW1[i] = Wh_w1[i];
    for (int i = tid; i < 128 * 128; i += 256) sW2[i] = Wh_w2[i];
    if (tid < 128) { sB1[tid] = Wh_b1[tid]; sB2[tid] = Wh_b2[tid]; }
    __syncthreads();

    int col = tid & 127, grp = tid >> 7;
    int jb = grp * 8;
    int ntiles = (NN + PH_NB - 1) / PH_NB;

    for (int tile = blockIdx.x; tile < ntiles; tile += gridDim.x) {
        int n0 = tile * PH_NB;
        __syncthreads();  // protect sIn/sHid reuse
        for (int i = tid; i < PH_NB * HH; i += 256) {
            int j = i / HH, k = i % HH;
            int n = n0 + j;
            float hv = 0.f, mv = 0.f;
            if (n < NN) { hv = h[(size_t)n * HH + k]; mv = g_msg[(size_t)n * HH + k]; }
            sIn[j * 256 + k]       = hv;
            sIn[j * 256 + 128 + k] = mv;
        }
        __syncthreads();

        float acc[8];
        {
            float b = sB1[col];
#pragma unroll
            for (int j = 0; j < 8; j++) acc[j] = b;
        }
        for (int k = 0; k < 256; k++) {
            float w = sW1[k * 128 + col];
#pragma unroll
            for (int j = 0; j < 8; j++)
                acc[j] = fmaf(sIn[(jb + j) * 256 + k], w, acc[j]);
        }
#pragma unroll
        for (int j = 0; j < 8; j++)
            sHid[col * 17 + jb + j] = silu_f(acc[j]);
        __syncthreads();

        float acc2[8];
        {
            float b = sB2[col];
#pragma unroll
            for (int j = 0; j < 8; j++) acc2[j] = b;
        }
        for (int k = 0; k < 128; k++) {
            float w = sW2[k * 128 + col];
#pragma unroll
            for (int j = 0; j < 8; j++)
                acc2[j] = fmaf(sHid[k * 17 + jb + j], w, acc2[j]);
        }
#pragma unroll
        for (int j = 0; j < 8; j++) {
            int n = n0 + jb + j;
            if (n < NN)
                out[(size_t)n * HH + col] = h[(size_t)n * HH + col] + acc2[j];
        }
        if (tid < PH_NB * 3) {
            int n = n0 + tid / 3;
            if (n < NN) {
                int c = tid % 3;
                out[(size_t)NN * HH + n * 3 + c] = x[n * 3 + c] + g_coord[n * 3 + c];
            }
        }
    }
}

// ---------------- launch ----------------
extern "C" void kernel_launch(void* const* d_in, const int* in_sizes, int n_in,
                              void* d_out, int out_size) {
    const float* h         = (const float*)d_in[0];
    const float* x         = (const float*)d_in[1];
    const void*  ei        = d_in[2];
    const float* edge_attr = (const float*)d_in[3];
    const float* t_emb     = (const float*)d_in[4];
    const float* We_w1     = (const float*)d_in[5];
    const float* We_b1     = (const float*)d_in[6];
    const float* We_w2     = (const float*)d_in[7];
    const float* We_b2     = (const float*)d_in[8];
    const float* Watt_w    = (const float*)d_in[9];
    const float* Watt_b    = (const float*)d_in[10];
    const float* Wx_w1     = (const float*)d_in[11];
    const float* Wx_b1     = (const float*)d_in[12];
    const float* Wx_w2     = (const float*)d_in[13];
    const float* Wx_b2     = (const float*)d_in[14];
    const float* Wx_w3     = (const float*)d_in[15];
    const float* Wh_w1     = (const float*)d_in[16];
    const float* Wh_b1     = (const float*)d_in[17];
    const float* Wh_w2     = (const float*)d_in[18];
    const float* Wh_b2     = (const float*)d_in[19];
    float* out = (float*)d_out;

    int nsm = 148;
    cudaDeviceGetAttribute(&nsm, cudaDevAttrMultiProcessorCount, 0);

    cudaFuncSetAttribute(edge_kernel, cudaFuncAttributeMaxDynamicSharedMemorySize, EDGE_SMEM_BYTES);
    cudaFuncSetAttribute(node_out_kernel, cudaFuncAttributeMaxDynamicSharedMemorySize, NODE_SMEM_BYTES);

    detect_kernel<<<1, 256>>>(ei);
    precompute_kernel<<<(NN + PC_NB - 1) / PC_NB, 128>>>(h, t_emb, We_w1, We_b1, Wx_w1, Wx_b1);
    edge_kernel<<<nsm, 256, EDGE_SMEM_BYTES>>>(x, ei, edge_attr,
                                               We_w2, We_b2, Watt_w, Watt_b,
                                               Wx_w2, Wx_b2, Wx_w3, We_w1, Wx_w1);
    node_out_kernel<<<nsm, 256, NODE_SMEM_BYTES>>>(h, x, Wh_w1, Wh_b1, Wh_w2, Wh_b2, out);
}

// round 3
// speedup vs baseline: 1.1453x; 1.1453x over previous
#include <cuda_runtime.h>
#include <math.h>

#define NN 50000
#define NE 600000
#define HH 128
#define EDD 16
#define TDD 32

#define ET 32      // edges per tile
#define EG 8       // edges per thread group
#define NG 4       // groups of 128 threads
#define PC_NB 8    // nodes per block, precompute
#define PH_NB 16   // nodes per tile, phi_h
#define PH_PAD 20  // padded node stride in transposed node-kernel staging

static_assert(NE % ET == 0, "tile divides E");
static_assert(NN % PC_NB == 0, "precompute exact");
static_assert(NN % PH_NB == 0, "node tile exact");

// ---------------- device scratch ----------------
__device__ float g_A1[NN * HH];
__device__ float g_A2[NN * HH];
__device__ float g_B1[NN * HH];
__device__ float g_B2[NN * HH];
__device__ float g_msg[NN * HH];
__device__ float g_coord[NN * 3];
__device__ int   g_is64;

typedef unsigned long long u64;

__device__ __forceinline__ u64 pk(float lo, float hi) {
    u64 r; asm("mov.b64 %0,{%1,%2};" : "=l"(r) : "f"(lo), "f"(hi)); return r;
}
__device__ __forceinline__ void upk(float& lo, float& hi, u64 v) {
    asm("mov.b64 {%0,%1},%2;" : "=f"(lo), "=f"(hi) : "l"(v));
}
__device__ __forceinline__ u64 f2fma(u64 a, u64 b, u64 c) {
    u64 d; asm("fma.rn.f32x2 %0,%1,%2,%3;" : "=l"(d) : "l"(a), "l"(b), "l"(c)); return d;
}

__device__ __forceinline__ float silu_f(float v) {
    return v / (1.f + __expf(-v));
}

// ---------------- int32 vs int64 edge_index detection ----------------
__global__ void detect_kernel(const void* __restrict__ ei) {
    __shared__ int ok;
    if (threadIdx.x == 0) ok = 1;
    __syncthreads();
    const long long* p = (const long long*)ei;
    long long v = p[threadIdx.x];
    if (v < 0 || v >= NN) atomicExch(&ok, 0);
    __syncthreads();
    if (threadIdx.x == 0) g_is64 = ok;
}

// ---------------- per-node layer-1 partials (f32x2) ----------------
__global__ __launch_bounds__(128)
void precompute_kernel(const float* __restrict__ h, const float* __restrict__ t_emb,
                       const float* __restrict__ We_w1, const float* __restrict__ We_b1,
                       const float* __restrict__ Wx_w1, const float* __restrict__ Wx_b1)
{
    __shared__ float hbufT[HH * PC_NB];   // [k][j]
    __shared__ float tbufT[TDD * PC_NB];
    int col = threadIdx.x;
    int n0 = blockIdx.x * PC_NB;

    for (int i = col; i < PC_NB * HH; i += 128) {
        int j = i >> 7, k = i & 127;
        hbufT[k * PC_NB + j] = h[(size_t)(n0 + j) * HH + k];
    }
    for (int i = col; i < PC_NB * TDD; i += 128) {
        int j = i >> 5, k = i & 31;
        tbufT[k * PC_NB + j] = t_emb[(size_t)(n0 + j) * TDD + k];
    }
    __syncthreads();

    u64 a1[4], a2[4], b1[4], b2[4];
    {
        float be = We_b1[col], bx = Wx_b1[col];
        u64 pbe = pk(be, be), pbx = pk(bx, bx), z = pk(0.f, 0.f);
#pragma unroll
        for (int j = 0; j < 4; j++) { a1[j] = pbe; b1[j] = pbx; a2[j] = z; b2[j] = z; }
    }

#pragma unroll 2
    for (int k = 0; k < HH; k++) {
        float wa1 = We_w1[(size_t)k * HH + col];
        float wa2 = We_w1[(size_t)(HH + k) * HH + col];
        float wb1 = Wx_w1[(size_t)k * HH + col];
        float wb2 = Wx_w1[(size_t)(HH + k) * HH + col];
        u64 pa1 = pk(wa1, wa1), pa2 = pk(wa2, wa2);
        u64 pb1 = pk(wb1, wb1), pb2 = pk(wb2, wb2);
        const u64* ph = (const u64*)(hbufT + k * PC_NB);
#pragma unroll
        for (int j = 0; j < 4; j++) {
            u64 hv = ph[j];
            a1[j] = f2fma(hv, pa1, a1[j]);
            a2[j] = f2fma(hv, pa2, a2[j]);
            b1[j] = f2fma(hv, pb1, b1[j]);
            b2[j] = f2fma(hv, pb2, b2[j]);
        }
    }
#pragma unroll 2
    for (int k = 0; k < TDD; k++) {
        float wta = We_w1[(size_t)(273 + k) * HH + col];
        float wtb = Wx_w1[(size_t)(272 + k) * HH + col];
        u64 pta = pk(wta, wta), ptb = pk(wtb, wtb);
        const u64* pt = (const u64*)(tbufT + k * PC_NB);
#pragma unroll
        for (int j = 0; j < 4; j++) {
            u64 tv = pt[j];
            a1[j] = f2fma(tv, pta, a1[j]);
            b1[j] = f2fma(tv, ptb, b1[j]);
        }
    }
#pragma unroll
    for (int j = 0; j < 4; j++) {
        size_t o0 = (size_t)(n0 + 2 * j) * HH + col;
        size_t o1 = o0 + HH;
        float x0, x1;
        upk(x0, x1, a1[j]); g_A1[o0] = x0; g_A1[o1] = x1;
        upk(x0, x1, a2[j]); g_A2[o0] = x0; g_A2[o1] = x1;
        upk(x0, x1, b1[j]); g_B1[o0] = x0; g_B1[o1] = x1;
        upk(x0, x1, b2[j]); g_B2[o0] = x0; g_B2[o1] = x1;
        g_msg[o0] = 0.f; g_msg[o1] = 0.f;
    }
    if (col < PC_NB * 3) g_coord[n0 * 3 + col] = 0.f;
}

// ---------------- edge kernel: persistent, smem-resident weights ----------------
// smem float offsets
#define O_WE2   0
#define O_WX2   (O_WE2 + 128*128)
#define O_WEXTE (O_WX2 + 128*128)      // 17 x 128
#define O_WEXTX (O_WEXTE + 17*128)     // 16 x 128
#define O_WEB2  (O_WEXTX + 16*128)
#define O_WXB2  (O_WEB2 + 128)
#define O_WATT  (O_WXB2 + 128)
#define O_WX3   (O_WATT + 128)
#define O_EXT   (O_WX3 + 128)          // 17 x ET [row][edge]
#define O_DIFFN (O_EXT + 17*ET)        // 3 x ET
#define O_SRC   (O_DIFFN + 3*ET)       // ET ints
#define O_DST   (O_SRC + ET)           // ET ints
#define O_M1T   (O_DST + ET)           // 128 x 36 transposed activations
#define O_C1T   (O_M1T + 128*36)       // 128 x 36
#define O_REDA  (O_C1T + 128*36)       // NG x 4 warps x EG
#define O_REDC  (O_REDA + 128)         // NG x 4 warps x EG
#define EDGE_SMEM_FLOATS (O_REDC + 128)
#define EDGE_SMEM_BYTES  (EDGE_SMEM_FLOATS * 4)

__global__ __launch_bounds__(512, 1)
void edge_kernel(const float* __restrict__ x, const void* __restrict__ ei,
                 const float* __restrict__ edge_attr,
                 const float* __restrict__ We_w2, const float* __restrict__ We_b2,
                 const float* __restrict__ Watt_w, const float* __restrict__ Watt_b,
                 const float* __restrict__ Wx_w2, const float* __restrict__ Wx_b2,
                 const float* __restrict__ Wx_w3,
                 const float* __restrict__ We_w1, const float* __restrict__ Wx_w1)
{
    extern __shared__ float sm[];
    int tid = threadIdx.x;

    for (int i = tid; i < 128 * 128; i += 512) { sm[O_WE2 + i] = We_w2[i]; sm[O_WX2 + i] = Wx_w2[i]; }
    for (int i = tid; i < 17 * 128; i += 512) sm[O_WEXTE + i] = We_w1[256 * 128 + i];
    for (int i = tid; i < 16 * 128; i += 512) sm[O_WEXTX + i] = Wx_w1[256 * 128 + i];
    if (tid < 128) {
        sm[O_WEB2 + tid] = We_b2[tid];
        sm[O_WXB2 + tid] = Wx_b2[tid];
        sm[O_WATT + tid] = Watt_w[tid];
        sm[O_WX3  + tid] = Wx_w3[tid];
    }
    int is64 = g_is64;
    float attb = Watt_b[0];
    const long long* e64 = (const long long*)ei;
    const int*       e32 = (const int*)ei;
    int* sSrc = (int*)(sm + O_SRC);
    int* sDst = (int*)(sm + O_DST);

    int col = tid & 127;
    int grp = tid >> 7;        // 0..3
    int eb = grp * EG;
    int lane = tid & 31;
    int warp4 = (tid >> 5) & 3;

    for (int tile = blockIdx.x; tile < NE / ET; tile += gridDim.x) {
        int e0 = tile * ET;
        __syncthreads();  // staging protect (also covers initial weight loads)

        // ---- stage per-edge scalars ----
        if (tid < ET) {
            int e = e0 + tid;
            int s, d;
            if (is64) { s = (int)e64[e]; d = (int)e64[NE + e]; }
            else      { s = e32[e];      d = e32[NE + e]; }
            sSrc[tid] = s; sDst[tid] = d;
            float dx = x[s * 3 + 0] - x[d * 3 + 0];
            float dy = x[s * 3 + 1] - x[d * 3 + 1];
            float dz = x[s * 3 + 2] - x[d * 3 + 2];
            float dsq = dx * dx + dy * dy + dz * dz;
            float inv = 1.f / (sqrtf(dsq + 1e-8f) + 1.f);
            sm[O_EXT + 0 * ET + tid]   = dsq;
            sm[O_DIFFN + 0 * ET + tid] = dx * inv;
            sm[O_DIFFN + 1 * ET + tid] = dy * inv;
            sm[O_DIFFN + 2 * ET + tid] = dz * inv;
        }
        {   // ET*EDD == 512 == blockDim
            int e = tid >> 4, j = tid & 15;
            sm[O_EXT + (1 + j) * ET + e] = edge_attr[(size_t)(e0 + e) * EDD + j];
        }
        __syncthreads();

        // ---- phase A: layer-1 via node partials + K=17 ext GEMM (packed) ----
        float ug[EG], vg[EG];
#pragma unroll
        for (int q = 0; q < EG; q++) {
            int s = sSrc[eb + q], d = sDst[eb + q];
            ug[q] = g_A1[(size_t)s * HH + col] + g_A2[(size_t)d * HH + col];
            vg[q] = g_B1[(size_t)s * HH + col] + g_B2[(size_t)d * HH + col];
        }
        u64 u2[4], v2[4];
#pragma unroll
        for (int j = 0; j < 4; j++) { u2[j] = pk(ug[2*j], ug[2*j+1]); v2[j] = pk(vg[2*j], vg[2*j+1]); }

#pragma unroll
        for (int r = 0; r < 17; r++) {
            float we = sm[O_WEXTE + r * 128 + col];
            u64 we2 = pk(we, we);
            const u64* pe = (const u64*)(sm + O_EXT + r * ET + eb);
            u64 ev0 = pe[0], ev1 = pe[1], ev2 = pe[2], ev3 = pe[3];
            u2[0] = f2fma(ev0, we2, u2[0]);
            u2[1] = f2fma(ev1, we2, u2[1]);
            u2[2] = f2fma(ev2, we2, u2[2]);
            u2[3] = f2fma(ev3, we2, u2[3]);
            if (r >= 1) {
                float wx = sm[O_WEXTX + (r - 1) * 128 + col];
                u64 wx2 = pk(wx, wx);
                v2[0] = f2fma(ev0, wx2, v2[0]);
                v2[1] = f2fma(ev1, wx2, v2[1]);
                v2[2] = f2fma(ev2, wx2, v2[2]);
                v2[3] = f2fma(ev3, wx2, v2[3]);
            }
        }
#pragma unroll
        for (int j = 0; j < 4; j++) {
            float a, b;
            upk(a, b, u2[j]);
            *(float2*)(sm + O_M1T + col * 36 + eb + 2 * j) = make_float2(silu_f(a), silu_f(b));
            upk(a, b, v2[j]);
            *(float2*)(sm + O_C1T + col * 36 + eb + 2 * j) = make_float2(silu_f(a), silu_f(b));
        }
        __syncthreads();

        // ---- phase B: m2 = silu(u) @ We_w2 + b2 (f32x2) ----
        u64 acc[4];
        {
            float b = sm[O_WEB2 + col];
            u64 bb = pk(b, b);
            acc[0] = bb; acc[1] = bb; acc[2] = bb; acc[3] = bb;
        }
#pragma unroll 4
        for (int k = 0; k < 128; k++) {
            float w = sm[O_WE2 + k * 128 + col];
            u64 ww = pk(w, w);
            const u64* p = (const u64*)(sm + O_M1T + k * 36 + eb);
            acc[0] = f2fma(p[0], ww, acc[0]);
            acc[1] = f2fma(p[1], ww, acc[1]);
            acc[2] = f2fma(p[2], ww, acc[2]);
            acc[3] = f2fma(p[3], ww, acc[3]);
        }
        float m2[EG];
#pragma unroll
        for (int j = 0; j < 4; j++) upk(m2[2*j], m2[2*j+1], acc[j]);

        // att partial: reduce m2*wA over cols (4 warps per group)
        {
            float wA = sm[O_WATT + col];
            float pa[EG];
#pragma unroll
            for (int q = 0; q < EG; q++) pa[q] = m2[q] * wA;
#pragma unroll
            for (int msk = 16; msk > 0; msk >>= 1)
#pragma unroll
                for (int q = 0; q < EG; q++)
                    pa[q] += __shfl_xor_sync(0xffffffffu, pa[q], msk);
            if (lane == 0) {
#pragma unroll
                for (int q = 0; q < EG; q++)
                    sm[O_REDA + (grp * 4 + warp4) * EG + q] = pa[q];
            }
        }

        // ---- phase C: c2 = silu(v) @ Wx_w2 + b (f32x2); coord weight partial ----
        u64 acc2[4];
        {
            float b = sm[O_WXB2 + col];
            u64 bb = pk(b, b);
            acc2[0] = bb; acc2[1] = bb; acc2[2] = bb; acc2[3] = bb;
        }
#pragma unroll 4
        for (int k = 0; k < 128; k++) {
            float w = sm[O_WX2 + k * 128 + col];
            u64 ww = pk(w, w);
            const u64* p = (const u64*)(sm + O_C1T + k * 36 + eb);
            acc2[0] = f2fma(p[0], ww, acc2[0]);
            acc2[1] = f2fma(p[1], ww, acc2[1]);
            acc2[2] = f2fma(p[2], ww, acc2[2]);
            acc2[3] = f2fma(p[3], ww, acc2[3]);
        }
        {
            float wC = sm[O_WX3 + col];
            float pc[EG];
#pragma unroll
            for (int j = 0; j < 4; j++) {
                float a, b;
                upk(a, b, acc2[j]);
                pc[2*j]   = silu_f(a) * wC;
                pc[2*j+1] = silu_f(b) * wC;
            }
#pragma unroll
            for (int msk = 16; msk > 0; msk >>= 1)
#pragma unroll
                for (int q = 0; q < EG; q++)
                    pc[q] += __shfl_xor_sync(0xffffffffu, pc[q], msk);
            if (lane == 0) {
#pragma unroll
                for (int q = 0; q < EG; q++)
                    sm[O_REDC + (grp * 4 + warp4) * EG + q] = pc[q];
            }
        }
        __syncthreads();

        // ---- epilogue: attention + msg atomics; coord weight + coord atomics ----
#pragma unroll
        for (int q = 0; q < EG; q++) {
            float s = sm[O_REDA + (grp * 4 + 0) * EG + q] + sm[O_REDA + (grp * 4 + 1) * EG + q]
                    + sm[O_REDA + (grp * 4 + 2) * EG + q] + sm[O_REDA + (grp * 4 + 3) * EG + q];
            float att = 1.f / (1.f + __expf(-(s + attb)));
            atomicAdd(&g_msg[(size_t)sDst[eb + q] * HH + col], att * m2[q]);
        }
        if (col < EG) {
            int e = eb + col;
            float s = sm[O_REDC + (grp * 4 + 0) * EG + col] + sm[O_REDC + (grp * 4 + 1) * EG + col]
                    + sm[O_REDC + (grp * 4 + 2) * EG + col] + sm[O_REDC + (grp * 4 + 3) * EG + col];
            float cw = tanhf(s) * 2.5f;
            int d = sDst[e];
            atomicAdd(&g_coord[d * 3 + 0], sm[O_DIFFN + 0 * ET + e] * cw);
            atomicAdd(&g_coord[d * 3 + 1], sm[O_DIFFN + 1 * ET + e] * cw);
            atomicAdd(&g_coord[d * 3 + 2], sm[O_DIFFN + 2 * ET + e] * cw);
        }
    }
}

// ---------------- phi_h + output assembly (f32x2, 512 threads) ----------------
#define NODE_SMEM_FLOATS (256*128 + 128*128 + 128 + 128 + 256*PH_PAD + 128*PH_PAD)
#define NODE_SMEM_BYTES  (NODE_SMEM_FLOATS * 4)

__global__ __launch_bounds__(512, 1)
void node_out_kernel(const float* __restrict__ h, const float* __restrict__ x,
                     const float* __restrict__ Wh_w1, const float* __restrict__ Wh_b1,
                     const float* __restrict__ Wh_w2, const float* __restrict__ Wh_b2,
                     float* __restrict__ out)
{
    extern __shared__ float sm[];
    float* sW1   = sm;                       // 256 x 128
    float* sW2   = sW1 + 256 * 128;          // 128 x 128
    float* sB1   = sW2 + 128 * 128;          // 128
    float* sB2   = sB1 + 128;                // 128
    float* sInT  = sB2 + 128;                // [256][PH_PAD] transposed
    float* sHidT = sInT + 256 * PH_PAD;      // [128][PH_PAD] transposed

    int tid = threadIdx.x;
    for (int i = tid; i < 256 * 128; i += 512) sW1[i] = Wh_w1[i];
    for (int i = tid; i < 128 * 128; i += 512) sW2[i] = Wh_w2[i];
    if (tid < 128) { sB1[tid] = Wh_b1[tid]; sB2[tid] = Wh_b2[tid]; }

    int col = tid & 127, grp = tid >> 7;
    int jb = grp * 4;

    for (int tile = blockIdx.x; tile < NN / PH_NB; tile += gridDim.x) {
        int n0 = tile * PH_NB;
        __syncthreads();  // staging protect (also covers weight loads)
        for (int i = tid; i < PH_NB * HH; i += 512) {
            int j = i >> 7, k = i & 127;
            int n = n0 + j;
            sInT[k * PH_PAD + j]        = h[(size_t)n * HH + k];
            sInT[(HH + k) * PH_PAD + j] = g_msg[(size_t)n * HH + k];
        }
        __syncthreads();

        u64 acc[2];
        {
            float b = sB1[col]; u64 bb = pk(b, b);
            acc[0] = bb; acc[1] = bb;
        }
#pragma unroll 4
        for (int k = 0; k < 256; k++) {
            float w = sW1[k * 128 + col];
            u64 ww = pk(w, w);
            const u64* p = (const u64*)(sInT + k * PH_PAD + jb);
            acc[0] = f2fma(p[0], ww, acc[0]);
            acc[1] = f2fma(p[1], ww, acc[1]);
        }
        {
            float a, b;
            upk(a, b, acc[0]);
            sHidT[col * PH_PAD + jb + 0] = silu_f(a);
            sHidT[col * PH_PAD + jb + 1] = silu_f(b);
            upk(a, b, acc[1]);
            sHidT[col * PH_PAD + jb + 2] = silu_f(a);
            sHidT[col * PH_PAD + jb + 3] = silu_f(b);
        }
        __syncthreads();

        u64 acc2[2];
        {
            float b = sB2[col]; u64 bb = pk(b, b);
            acc2[0] = bb; acc2[1] = bb;
        }
#pragma unroll 4
        for (int k = 0; k < 128; k++) {
            float w = sW2[k * 128 + col];
            u64 ww = pk(w, w);
            const u64* p = (const u64*)(sHidT + k * PH_PAD + jb);
            acc2[0] = f2fma(p[0], ww, acc2[0]);
            acc2[1] = f2fma(p[1], ww, acc2[1]);
        }
        {
            float a, b;
            upk(a, b, acc2[0]);
            out[(size_t)(n0 + jb + 0) * HH + col] = h[(size_t)(n0 + jb + 0) * HH + col] + a;
            out[(size_t)(n0 + jb + 1) * HH + col] = h[(size_t)(n0 + jb + 1) * HH + col] + b;
            upk(a, b, acc2[1]);
            out[(size_t)(n0 + jb + 2) * HH + col] = h[(size_t)(n0 + jb + 2) * HH + col] + a;
            out[(size_t)(n0 + jb + 3) * HH + col] = h[(size_t)(n0 + jb + 3) * HH + col] + b;
        }
        if (tid < PH_NB * 3) {
            int n = n0 + tid / 3, c = tid % 3;
            out[(size_t)NN * HH + n * 3 + c] = x[n * 3 + c] + g_coord[n * 3 + c];
        }
    }
}

// ---------------- launch ----------------
extern "C" void kernel_launch(void* const* d_in, const int* in_sizes, int n_in,
                              void* d_out, int out_size) {
    const float* h         = (const float*)d_in[0];
    const float* x         = (const float*)d_in[1];
    const void*  ei        = d_in[2];
    const float* edge_attr = (const float*)d_in[3];
    const float* t_emb     = (const float*)d_in[4];
    const float* We_w1     = (const float*)d_in[5];
    const float* We_b1     = (const float*)d_in[6];
    const float* We_w2     = (const float*)d_in[7];
    const float* We_b2     = (const float*)d_in[8];
    const float* Watt_w    = (const float*)d_in[9];
    const float* Watt_b    = (const float*)d_in[10];
    const float* Wx_w1     = (const float*)d_in[11];
    const float* Wx_b1     = (const float*)d_in[12];
    const float* Wx_w2     = (const float*)d_in[13];
    const float* Wx_b2     = (const float*)d_in[14];
    const float* Wx_w3     = (const float*)d_in[15];
    const float* Wh_w1     = (const float*)d_in[16];
    const float* Wh_b1     = (const float*)d_in[17];
    const float* Wh_w2     = (const float*)d_in[18];
    const float* Wh_b2     = (const float*)d_in[19];
    float* out = (float*)d_out;

    int nsm = 148;
    cudaDeviceGetAttribute(&nsm, cudaDevAttrMultiProcessorCount, 0);

    cudaFuncSetAttribute(edge_kernel, cudaFuncAttributeMaxDynamicSharedMemorySize, EDGE_SMEM_BYTES);
    cudaFuncSetAttribute(node_out_kernel, cudaFuncAttributeMaxDynamicSharedMemorySize, NODE_SMEM_BYTES);

    detect_kernel<<<1, 256>>>(ei);
    precompute_kernel<<<NN / PC_NB, 128>>>(h, t_emb, We_w1, We_b1, Wx_w1, Wx_b1);
    edge_kernel<<<nsm, 512, EDGE_SMEM_BYTES>>>(x, ei, edge_attr,
                                               We_w2, We_b2, Watt_w, Watt_b,
                                               Wx_w2, Wx_b2, Wx_w3, We_w1, Wx_w1);
    node_out_kernel<<<nsm, 512, NODE_SMEM_BYTES>>>(h, x, Wh_w1, Wh_b1, Wh_w2, Wh_b2, out);
}

// round 4
// speedup vs baseline: 1.3573x; 1.1851x over previous
#include <cuda_runtime.h>
#include <math.h>

#define NN 50000
#define NE 600000
#define HH 128
#define EDD 16
#define TDD 32

#define ET 128     // edges per block (E1/E2)
#define PC_NB 8
#define PH_NB 16
#define PH_PAD 20

static_assert(NN % PC_NB == 0, "precompute exact");
static_assert(NN % PH_NB == 0, "node tile exact");

// ---------------- device scratch ----------------
__device__ float g_A1[NN * HH];
__device__ float g_A2[NN * HH];
__device__ float g_B1[NN * HH];
__device__ float g_B2[NN * HH];
__device__ float g_msg[NN * HH];
__device__ float g_coord[NN * 3];
__device__ int   g_is64;

typedef unsigned long long u64;

__device__ __forceinline__ u64 pk(float lo, float hi) {
    u64 r; asm("mov.b64 %0,{%1,%2};" : "=l"(r) : "f"(lo), "f"(hi)); return r;
}
__device__ __forceinline__ void upk(float& lo, float& hi, u64 v) {
    asm("mov.b64 {%0,%1},%2;" : "=f"(lo), "=f"(hi) : "l"(v));
}
__device__ __forceinline__ u64 f2fma(u64 a, u64 b, u64 c) {
    u64 d; asm("fma.rn.f32x2 %0,%1,%2,%3;" : "=l"(d) : "l"(a), "l"(b), "l"(c)); return d;
}
__device__ __forceinline__ u64 f2add(u64 a, u64 b) {
    u64 d; asm("add.rn.f32x2 %0,%1,%2;" : "=l"(d) : "l"(a), "l"(b)); return d;
}
__device__ __forceinline__ float silu_f(float v) {
    return v / (1.f + __expf(-v));
}

// ---------------- int32 vs int64 edge_index detection ----------------
__global__ void detect_kernel(const void* __restrict__ ei) {
    __shared__ int ok;
    if (threadIdx.x == 0) ok = 1;
    __syncthreads();
    const long long* p = (const long long*)ei;
    long long v = p[threadIdx.x];
    if (v < 0 || v >= NN) atomicExch(&ok, 0);
    __syncthreads();
    if (threadIdx.x == 0) g_is64 = ok;
}

// ---------------- per-node layer-1 partials (f32x2) ----------------
__global__ __launch_bounds__(128)
void precompute_kernel(const float* __restrict__ h, const float* __restrict__ t_emb,
                       const float* __restrict__ We_w1, const float* __restrict__ We_b1,
                       const float* __restrict__ Wx_w1, const float* __restrict__ Wx_b1)
{
    __shared__ float hbufT[HH * PC_NB];
    __shared__ float tbufT[TDD * PC_NB];
    int col = threadIdx.x;
    int n0 = blockIdx.x * PC_NB;

    for (int i = col; i < PC_NB * HH; i += 128) {
        int j = i >> 7, k = i & 127;
        hbufT[k * PC_NB + j] = h[(size_t)(n0 + j) * HH + k];
    }
    for (int i = col; i < PC_NB * TDD; i += 128) {
        int j = i >> 5, k = i & 31;
        tbufT[k * PC_NB + j] = t_emb[(size_t)(n0 + j) * TDD + k];
    }
    __syncthreads();

    u64 a1[4], a2[4], b1[4], b2[4];
    {
        float be = We_b1[col], bx = Wx_b1[col];
        u64 pbe = pk(be, be), pbx = pk(bx, bx), z = pk(0.f, 0.f);
#pragma unroll
        for (int j = 0; j < 4; j++) { a1[j] = pbe; b1[j] = pbx; a2[j] = z; b2[j] = z; }
    }
#pragma unroll 2
    for (int k = 0; k < HH; k++) {
        float wa1 = We_w1[(size_t)k * HH + col];
        float wa2 = We_w1[(size_t)(HH + k) * HH + col];
        float wb1 = Wx_w1[(size_t)k * HH + col];
        float wb2 = Wx_w1[(size_t)(HH + k) * HH + col];
        u64 pa1 = pk(wa1, wa1), pa2 = pk(wa2, wa2);
        u64 pb1 = pk(wb1, wb1), pb2 = pk(wb2, wb2);
        const u64* ph = (const u64*)(hbufT + k * PC_NB);
#pragma unroll
        for (int j = 0; j < 4; j++) {
            u64 hv = ph[j];
            a1[j] = f2fma(hv, pa1, a1[j]);
            a2[j] = f2fma(hv, pa2, a2[j]);
            b1[j] = f2fma(hv, pb1, b1[j]);
            b2[j] = f2fma(hv, pb2, b2[j]);
        }
    }
#pragma unroll 2
    for (int k = 0; k < TDD; k++) {
        float wta = We_w1[(size_t)(273 + k) * HH + col];
        float wtb = Wx_w1[(size_t)(272 + k) * HH + col];
        u64 pta = pk(wta, wta), ptb = pk(wtb, wtb);
        const u64* pt = (const u64*)(tbufT + k * PC_NB);
#pragma unroll
        for (int j = 0; j < 4; j++) {
            u64 tv = pt[j];
            a1[j] = f2fma(tv, pta, a1[j]);
            b1[j] = f2fma(tv, ptb, b1[j]);
        }
    }
#pragma unroll
    for (int j = 0; j < 4; j++) {
        size_t o0 = (size_t)(n0 + 2 * j) * HH + col;
        size_t o1 = o0 + HH;
        float x0, x1;
        upk(x0, x1, a1[j]); g_A1[o0] = x0; g_A1[o1] = x1;
        upk(x0, x1, a2[j]); g_A2[o0] = x0; g_A2[o1] = x1;
        upk(x0, x1, b1[j]); g_B1[o0] = x0; g_B1[o1] = x1;
        upk(x0, x1, b2[j]); g_B2[o0] = x0; g_B2[o1] = x1;
        g_msg[o0] = 0.f; g_msg[o1] = 0.f;
    }
    if (col < PC_NB * 3) g_coord[n0 * 3 + col] = 0.f;
}

// ================= E1: message path (phi_e + attention + msg scatter) =================
#define E1_W2    0
#define E1_WEXT  (E1_W2 + 16384)        // 17 x 128 (We_w1 rows 256..272)
#define E1_WATT  (E1_WEXT + 2176)
#define E1_B2    (E1_WATT + 128)
#define E1_EXT   (E1_B2 + 128)          // 17 x 128 [row][edge]
#define E1_SRC   (E1_EXT + 2176)
#define E1_DST   (E1_SRC + 128)
#define E1_M1T   (E1_DST + 128)         // 128 x 132 [k][edge]
#define E1_RED   (E1_M1T + 128*132)     // 16 warps x 16
#define E1_ATT   (E1_RED + 256)
#define E1_SIZE  (E1_ATT + 128)
#define E1_BYTES (E1_SIZE * 4)

__global__ __launch_bounds__(512, 1)
void e1_kernel(const float* __restrict__ x, const void* __restrict__ ei,
               const float* __restrict__ edge_attr,
               const float* __restrict__ We_w1,
               const float* __restrict__ We_w2, const float* __restrict__ We_b2,
               const float* __restrict__ Watt_w, const float* __restrict__ Watt_b)
{
    extern __shared__ float sm[];
    int tid = threadIdx.x;
    int e0 = blockIdx.x * ET;
    int is64 = g_is64;

    // weights
    for (int i = tid; i < 16384; i += 512) sm[E1_W2 + i] = We_w2[i];
    for (int i = tid; i < 2176; i += 512) sm[E1_WEXT + i] = We_w1[256 * 128 + i];
    if (tid < 128) { sm[E1_WATT + tid] = Watt_w[tid]; sm[E1_B2 + tid] = We_b2[tid]; }

    int* sSrc = (int*)(sm + E1_SRC);
    int* sDst = (int*)(sm + E1_DST);

    // stage per-edge scalars
    if (tid < ET) {
        int ge = e0 + tid;
        int s = 0, d = 0;
        if (ge < NE) {
            if (is64) { const long long* p = (const long long*)ei; s = (int)p[ge]; d = (int)p[NE + ge]; }
            else      { const int* p = (const int*)ei;             s = p[ge];      d = p[NE + ge]; }
        }
        sSrc[tid] = s; sDst[tid] = d;
        float dx = x[s * 3 + 0] - x[d * 3 + 0];
        float dy = x[s * 3 + 1] - x[d * 3 + 1];
        float dz = x[s * 3 + 2] - x[d * 3 + 2];
        sm[E1_EXT + tid] = dx * dx + dy * dy + dz * dz;
    }
    for (int idx = tid; idx < ET * EDD; idx += 512) {
        int j = idx >> 7, e = idx & 127;
        int ge = e0 + e;
        sm[E1_EXT + (1 + j) * 128 + e] = (ge < NE) ? edge_attr[(size_t)ge * EDD + j] : 0.f;
    }
    __syncthreads();

    // ---- phase A: u = A1[s]+A2[d] + ext@Wext ; silu ; store transposed ----
    {
        int e = tid & 127, cg = tid >> 7;   // 32 cols per thread
        int s = sSrc[e], d = sDst[e];
        const ulonglong2* a1p = (const ulonglong2*)(g_A1 + (size_t)s * HH + cg * 32);
        const ulonglong2* a2p = (const ulonglong2*)(g_A2 + (size_t)d * HH + cg * 32);
        u64 u[16];
#pragma unroll
        for (int i = 0; i < 8; i++) {
            ulonglong2 va = a1p[i], vb = a2p[i];
            u[2 * i]     = f2add(va.x, vb.x);
            u[2 * i + 1] = f2add(va.y, vb.y);
        }
#pragma unroll 1
        for (int r = 0; r < 17; r++) {
            float ev = sm[E1_EXT + r * 128 + e];
            u64 ev2 = pk(ev, ev);
            const ulonglong2* wp = (const ulonglong2*)(sm + E1_WEXT + r * 128 + cg * 32);
#pragma unroll
            for (int i = 0; i < 8; i++) {
                ulonglong2 w = wp[i];
                u[2 * i]     = f2fma(ev2, w.x, u[2 * i]);
                u[2 * i + 1] = f2fma(ev2, w.y, u[2 * i + 1]);
            }
        }
#pragma unroll
        for (int i = 0; i < 16; i++) {
            float a, b; upk(a, b, u[i]);
            sm[E1_M1T + (cg * 32 + 2 * i) * 132 + e]     = silu_f(a);
            sm[E1_M1T + (cg * 32 + 2 * i + 1) * 132 + e] = silu_f(b);
        }
    }
    __syncthreads();

    // ---- GEMM: m2 = m1 @ We_w2 + b2 ; thread = (c in 0..63, eg in 0..7), TE=16, TC=2 ----
    int c = tid & 63, eg = tid >> 6;
    u64 acc0[8], acc1[8];
    {
        float b0 = sm[E1_B2 + c], b1 = sm[E1_B2 + c + 64];
        u64 p0 = pk(b0, b0), p1 = pk(b1, b1);
#pragma unroll
        for (int q = 0; q < 8; q++) { acc0[q] = p0; acc1[q] = p1; }
    }
#pragma unroll 4
    for (int k = 0; k < 128; k++) {
        float w0 = sm[E1_W2 + k * 128 + c];
        float w1 = sm[E1_W2 + k * 128 + c + 64];
        u64 ww0 = pk(w0, w0), ww1 = pk(w1, w1);
        const ulonglong2* mp = (const ulonglong2*)(sm + E1_M1T + k * 132 + eg * 16);
        ulonglong2 m0 = mp[0], m1 = mp[1], m2 = mp[2], m3 = mp[3];
        acc0[0] = f2fma(m0.x, ww0, acc0[0]); acc1[0] = f2fma(m0.x, ww1, acc1[0]);
        acc0[1] = f2fma(m0.y, ww0, acc0[1]); acc1[1] = f2fma(m0.y, ww1, acc1[1]);
        acc0[2] = f2fma(m1.x, ww0, acc0[2]); acc1[2] = f2fma(m1.x, ww1, acc1[2]);
        acc0[3] = f2fma(m1.y, ww0, acc0[3]); acc1[3] = f2fma(m1.y, ww1, acc1[3]);
        acc0[4] = f2fma(m2.x, ww0, acc0[4]); acc1[4] = f2fma(m2.x, ww1, acc1[4]);
        acc0[5] = f2fma(m2.y, ww0, acc0[5]); acc1[5] = f2fma(m2.y, ww1, acc1[5]);
        acc0[6] = f2fma(m3.x, ww0, acc0[6]); acc1[6] = f2fma(m3.x, ww1, acc1[6]);
        acc0[7] = f2fma(m3.y, ww0, acc0[7]); acc1[7] = f2fma(m3.y, ww1, acc1[7]);
    }

    // attention partial: pa[e-pair] = sum over this thread's 2 cols of m2*Watt
    {
        float wa0 = sm[E1_WATT + c], wa1 = sm[E1_WATT + c + 64];
        u64 pwa0 = pk(wa0, wa0), pwa1 = pk(wa1, wa1), z = pk(0.f, 0.f);
        u64 pa[8];
#pragma unroll
        for (int q = 0; q < 8; q++)
            pa[q] = f2fma(acc0[q], pwa0, f2fma(acc1[q], pwa1, z));
#pragma unroll
        for (int msk = 16; msk > 0; msk >>= 1)
#pragma unroll
            for (int q = 0; q < 8; q++)
                pa[q] = f2add(pa[q], __shfl_xor_sync(0xffffffffu, pa[q], msk));
        if ((tid & 31) == 0) {
            int warp = tid >> 5;
            u64* red = (u64*)(sm + E1_RED);
#pragma unroll
            for (int q = 0; q < 8; q++) red[warp * 8 + q] = pa[q];
        }
    }
    __syncthreads();

    if (tid < ET) {
        int e = tid, g2 = (e >> 4) * 2, q = e & 15;
        float s = sm[E1_RED + g2 * 16 + q] + sm[E1_RED + (g2 + 1) * 16 + q];
        sm[E1_ATT + e] = 1.f / (1.f + __expf(-(s + Watt_b[0])));
    }
    __syncthreads();

    // msg scatter
#pragma unroll
    for (int q = 0; q < 8; q++) {
        int e = eg * 16 + 2 * q;
        if (e0 + e < NE) {   // NE even, pairs never straddle
            float att0 = sm[E1_ATT + e], att1 = sm[E1_ATT + e + 1];
            int d0 = sDst[e], d1 = sDst[e + 1];
            float a, b;
            upk(a, b, acc0[q]);
            atomicAdd(&g_msg[(size_t)d0 * HH + c], att0 * a);
            atomicAdd(&g_msg[(size_t)d1 * HH + c], att1 * b);
            upk(a, b, acc1[q]);
            atomicAdd(&g_msg[(size_t)d0 * HH + c + 64], att0 * a);
            atomicAdd(&g_msg[(size_t)d1 * HH + c + 64], att1 * b);
        }
    }
}

// ================= E2: coord path (phi_x + coord scatter) =================
#define E2_W2    0
#define E2_WEXT  (E2_W2 + 16384)        // 16 x 128 (Wx_w1 rows 256..271)
#define E2_WX3   (E2_WEXT + 2048)
#define E2_B2    (E2_WX3 + 128)
#define E2_EXT   (E2_B2 + 128)          // 16 x 128
#define E2_DIFFN (E2_EXT + 2048)        // 3 x 128
#define E2_SRC   (E2_DIFFN + 384)
#define E2_DST   (E2_SRC + 128)
#define E2_C1T   (E2_DST + 128)         // 128 x 132
#define E2_RED   (E2_C1T + 128*132)     // 16 x 16
#define E2_SIZE  (E2_RED + 256)
#define E2_BYTES (E2_SIZE * 4)

__global__ __launch_bounds__(512, 1)
void e2_kernel(const float* __restrict__ x, const void* __restrict__ ei,
               const float* __restrict__ edge_attr,
               const float* __restrict__ Wx_w1,
               const float* __restrict__ Wx_w2, const float* __restrict__ Wx_b2,
               const float* __restrict__ Wx_w3)
{
    extern __shared__ float sm[];
    int tid = threadIdx.x;
    int e0 = blockIdx.x * ET;
    int is64 = g_is64;

    for (int i = tid; i < 16384; i += 512) sm[E2_W2 + i] = Wx_w2[i];
    for (int i = tid; i < 2048; i += 512) sm[E2_WEXT + i] = Wx_w1[256 * 128 + i];
    if (tid < 128) { sm[E2_WX3 + tid] = Wx_w3[tid]; sm[E2_B2 + tid] = Wx_b2[tid]; }

    int* sSrc = (int*)(sm + E2_SRC);
    int* sDst = (int*)(sm + E2_DST);

    if (tid < ET) {
        int ge = e0 + tid;
        int s = 0, d = 0;
        if (ge < NE) {
            if (is64) { const long long* p = (const long long*)ei; s = (int)p[ge]; d = (int)p[NE + ge]; }
            else      { const int* p = (const int*)ei;             s = p[ge];      d = p[NE + ge]; }
        }
        sSrc[tid] = s; sDst[tid] = d;
        float dx = x[s * 3 + 0] - x[d * 3 + 0];
        float dy = x[s * 3 + 1] - x[d * 3 + 1];
        float dz = x[s * 3 + 2] - x[d * 3 + 2];
        float dsq = dx * dx + dy * dy + dz * dz;
        float inv = 1.f / (sqrtf(dsq + 1e-8f) + 1.f);
        sm[E2_DIFFN + 0 * 128 + tid] = dx * inv;
        sm[E2_DIFFN + 1 * 128 + tid] = dy * inv;
        sm[E2_DIFFN + 2 * 128 + tid] = dz * inv;
    }
    for (int idx = tid; idx < ET * EDD; idx += 512) {
        int j = idx >> 7, e = idx & 127;
        int ge = e0 + e;
        sm[E2_EXT + j * 128 + e] = (ge < NE) ? edge_attr[(size_t)ge * EDD + j] : 0.f;
    }
    __syncthreads();

    // phase A
    {
        int e = tid & 127, cg = tid >> 7;
        int s = sSrc[e], d = sDst[e];
        const ulonglong2* b1p = (const ulonglong2*)(g_B1 + (size_t)s * HH + cg * 32);
        const ulonglong2* b2p = (const ulonglong2*)(g_B2 + (size_t)d * HH + cg * 32);
        u64 u[16];
#pragma unroll
        for (int i = 0; i < 8; i++) {
            ulonglong2 va = b1p[i], vb = b2p[i];
            u[2 * i]     = f2add(va.x, vb.x);
            u[2 * i + 1] = f2add(va.y, vb.y);
        }
#pragma unroll 1
        for (int r = 0; r < 16; r++) {
            float ev = sm[E2_EXT + r * 128 + e];
            u64 ev2 = pk(ev, ev);
            const ulonglong2* wp = (const ulonglong2*)(sm + E2_WEXT + r * 128 + cg * 32);
#pragma unroll
            for (int i = 0; i < 8; i++) {
                ulonglong2 w = wp[i];
                u[2 * i]     = f2fma(ev2, w.x, u[2 * i]);
                u[2 * i + 1] = f2fma(ev2, w.y, u[2 * i + 1]);
            }
        }
#pragma unroll
        for (int i = 0; i < 16; i++) {
            float a, b; upk(a, b, u[i]);
            sm[E2_C1T + (cg * 32 + 2 * i) * 132 + e]     = silu_f(a);
            sm[E2_C1T + (cg * 32 + 2 * i + 1) * 132 + e] = silu_f(b);
        }
    }
    __syncthreads();

    // GEMM: c2 = c1 @ Wx_w2 + b
    int c = tid & 63, eg = tid >> 6;
    u64 acc0[8], acc1[8];
    {
        float b0 = sm[E2_B2 + c], b1 = sm[E2_B2 + c + 64];
        u64 p0 = pk(b0, b0), p1 = pk(b1, b1);
#pragma unroll
        for (int q = 0; q < 8; q++) { acc0[q] = p0; acc1[q] = p1; }
    }
#pragma unroll 4
    for (int k = 0; k < 128; k++) {
        float w0 = sm[E2_W2 + k * 128 + c];
        float w1 = sm[E2_W2 + k * 128 + c + 64];
        u64 ww0 = pk(w0, w0), ww1 = pk(w1, w1);
        const ulonglong2* mp = (const ulonglong2*)(sm + E2_C1T + k * 132 + eg * 16);
        ulonglong2 m0 = mp[0], m1 = mp[1], m2 = mp[2], m3 = mp[3];
        acc0[0] = f2fma(m0.x, ww0, acc0[0]); acc1[0] = f2fma(m0.x, ww1, acc1[0]);
        acc0[1] = f2fma(m0.y, ww0, acc0[1]); acc1[1] = f2fma(m0.y, ww1, acc1[1]);
        acc0[2] = f2fma(m1.x, ww0, acc0[2]); acc1[2] = f2fma(m1.x, ww1, acc1[2]);
        acc0[3] = f2fma(m1.y, ww0, acc0[3]); acc1[3] = f2fma(m1.y, ww1, acc1[3]);
        acc0[4] = f2fma(m2.x, ww0, acc0[4]); acc1[4] = f2fma(m2.x, ww1, acc1[4]);
        acc0[5] = f2fma(m2.y, ww0, acc0[5]); acc1[5] = f2fma(m2.y, ww1, acc1[5]);
        acc0[6] = f2fma(m3.x, ww0, acc0[6]); acc1[6] = f2fma(m3.x, ww1, acc1[6]);
        acc0[7] = f2fma(m3.y, ww0, acc0[7]); acc1[7] = f2fma(m3.y, ww1, acc1[7]);
    }

    // coord-weight partial: pc = sum_c silu(c2)*wx3
    {
        float w30 = sm[E2_WX3 + c], w31 = sm[E2_WX3 + c + 64];
        u64 pc[8];
#pragma unroll
        for (int q = 0; q < 8; q++) {
            float a, b, p0, p1;
            upk(a, b, acc0[q]);
            p0 = silu_f(a) * w30; p1 = silu_f(b) * w30;
            upk(a, b, acc1[q]);
            p0 += silu_f(a) * w31; p1 += silu_f(b) * w31;
            pc[q] = pk(p0, p1);
        }
#pragma unroll
        for (int msk = 16; msk > 0; msk >>= 1)
#pragma unroll
            for (int q = 0; q < 8; q++)
                pc[q] = f2add(pc[q], __shfl_xor_sync(0xffffffffu, pc[q], msk));
        if ((tid & 31) == 0) {
            int warp = tid >> 5;
            u64* red = (u64*)(sm + E2_RED);
#pragma unroll
            for (int q = 0; q < 8; q++) red[warp * 8 + q] = pc[q];
        }
    }
    __syncthreads();

    if (tid < ET && e0 + tid < NE) {
        int e = tid, g2 = (e >> 4) * 2, q = e & 15;
        float s = sm[E2_RED + g2 * 16 + q] + sm[E2_RED + (g2 + 1) * 16 + q];
        float cw = tanhf(s) * 2.5f;
        int d = sDst[e];
        atomicAdd(&g_coord[d * 3 + 0], sm[E2_DIFFN + 0 * 128 + e] * cw);
        atomicAdd(&g_coord[d * 3 + 1], sm[E2_DIFFN + 1 * 128 + e] * cw);
        atomicAdd(&g_coord[d * 3 + 2], sm[E2_DIFFN + 2 * 128 + e] * cw);
    }
}

// ---------------- phi_h + output assembly ----------------
#define NODE_SMEM_FLOATS (256*128 + 128*128 + 128 + 128 + 256*PH_PAD + 128*PH_PAD)
#define NODE_SMEM_BYTES  (NODE_SMEM_FLOATS * 4)

__global__ __launch_bounds__(512, 1)
void node_out_kernel(const float* __restrict__ h, const float* __restrict__ x,
                     const float* __restrict__ Wh_w1, const float* __restrict__ Wh_b1,
                     const float* __restrict__ Wh_w2, const float* __restrict__ Wh_b2,
                     float* __restrict__ out)
{
    extern __shared__ float sm[];
    float* sW1   = sm;
    float* sW2   = sW1 + 256 * 128;
    float* sB1   = sW2 + 128 * 128;
    float* sB2   = sB1 + 128;
    float* sInT  = sB2 + 128;
    float* sHidT = sInT + 256 * PH_PAD;

    int tid = threadIdx.x;
    for (int i = tid; i < 256 * 128; i += 512) sW1[i] = Wh_w1[i];
    for (int i = tid; i < 128 * 128; i += 512) sW2[i] = Wh_w2[i];
    if (tid < 128) { sB1[tid] = Wh_b1[tid]; sB2[tid] = Wh_b2[tid]; }

    int col = tid & 127, grp = tid >> 7;
    int jb = grp * 4;

    for (int tile = blockIdx.x; tile < NN / PH_NB; tile += gridDim.x) {
        int n0 = tile * PH_NB;
        __syncthreads();
        for (int i = tid; i < PH_NB * HH; i += 512) {
            int j = i >> 7, k = i & 127;
            int n = n0 + j;
            sInT[k * PH_PAD + j]        = h[(size_t)n * HH + k];
            sInT[(HH + k) * PH_PAD + j] = g_msg[(size_t)n * HH + k];
        }
        __syncthreads();

        u64 acc[2];
        {
            float b = sB1[col]; u64 bb = pk(b, b);
            acc[0] = bb; acc[1] = bb;
        }
#pragma unroll 4
        for (int k = 0; k < 256; k++) {
            float w = sW1[k * 128 + col];
            u64 ww = pk(w, w);
            const u64* p = (const u64*)(sInT + k * PH_PAD + jb);
            acc[0] = f2fma(p[0], ww, acc[0]);
            acc[1] = f2fma(p[1], ww, acc[1]);
        }
        {
            float a, b;
            upk(a, b, acc[0]);
            sHidT[col * PH_PAD + jb + 0] = silu_f(a);
            sHidT[col * PH_PAD + jb + 1] = silu_f(b);
            upk(a, b, acc[1]);
            sHidT[col * PH_PAD + jb + 2] = silu_f(a);
            sHidT[col * PH_PAD + jb + 3] = silu_f(b);
        }
        __syncthreads();

        u64 acc2[2];
        {
            float b = sB2[col]; u64 bb = pk(b, b);
            acc2[0] = bb; acc2[1] = bb;
        }
#pragma unroll 4
        for (int k = 0; k < 128; k++) {
            float w = sW2[k * 128 + col];
            u64 ww = pk(w, w);
            const u64* p = (const u64*)(sHidT + k * PH_PAD + jb);
            acc2[0] = f2fma(p[0], ww, acc2[0]);
            acc2[1] = f2fma(p[1], ww, acc2[1]);
        }
        {
            float a, b;
            upk(a, b, acc2[0]);
            out[(size_t)(n0 + jb + 0) * HH + col] = h[(size_t)(n0 + jb + 0) * HH + col] + a;
            out[(size_t)(n0 + jb + 1) * HH + col] = h[(size_t)(n0 + jb + 1) * HH + col] + b;
            upk(a, b, acc2[1]);
            out[(size_t)(n0 + jb + 2) * HH + col] = h[(size_t)(n0 + jb + 2) * HH + col] + a;
            out[(size_t)(n0 + jb + 3) * HH + col] = h[(size_t)(n0 + jb + 3) * HH + col] + b;
        }
        if (tid < PH_NB * 3) {
            int n = n0 + tid / 3, c = tid % 3;
            out[(size_t)NN * HH + n * 3 + c] = x[n * 3 + c] + g_coord[n * 3 + c];
        }
    }
}

// ---------------- launch ----------------
extern "C" void kernel_launch(void* const* d_in, const int* in_sizes, int n_in,
                              void* d_out, int out_size) {
    const float* h         = (const float*)d_in[0];
    const float* x         = (const float*)d_in[1];
    const void*  ei        = d_in[2];
    const float* edge_attr = (const float*)d_in[3];
    const float* t_emb     = (const float*)d_in[4];
    const float* We_w1     = (const float*)d_in[5];
    const float* We_b1     = (const float*)d_in[6];
    const float* We_w2     = (const float*)d_in[7];
    const float* We_b2     = (const float*)d_in[8];
    const float* Watt_w    = (const float*)d_in[9];
    const float* Watt_b    = (const float*)d_in[10];
    const float* Wx_w1     = (const float*)d_in[11];
    const float* Wx_b1     = (const float*)d_in[12];
    const float* Wx_w2     = (const float*)d_in[13];
    const float* Wx_b2     = (const float*)d_in[14];
    const float* Wx_w3     = (const float*)d_in[15];
    const float* Wh_w1     = (const float*)d_in[16];
    const float* Wh_b1     = (const float*)d_in[17];
    const float* Wh_w2     = (const float*)d_in[18];
    const float* Wh_b2     = (const float*)d_in[19];
    float* out = (float*)d_out;

    int nsm = 148;
    cudaDeviceGetAttribute(&nsm, cudaDevAttrMultiProcessorCount, 0);

    cudaFuncSetAttribute(e1_kernel, cudaFuncAttributeMaxDynamicSharedMemorySize, E1_BYTES);
    cudaFuncSetAttribute(e2_kernel, cudaFuncAttributeMaxDynamicSharedMemorySize, E2_BYTES);
    cudaFuncSetAttribute(node_out_kernel, cudaFuncAttributeMaxDynamicSharedMemorySize, NODE_SMEM_BYTES);

    int eblocks = (NE + ET - 1) / ET;

    detect_kernel<<<1, 256>>>(ei);
    precompute_kernel<<<NN / PC_NB, 128>>>(h, t_emb, We_w1, We_b1, Wx_w1, Wx_b1);
    e1_kernel<<<eblocks, 512, E1_BYTES>>>(x, ei, edge_attr, We_w1, We_w2, We_b2, Watt_w, Watt_b);
    e2_kernel<<<eblocks, 512, E2_BYTES>>>(x, ei, edge_attr, Wx_w1, Wx_w2, Wx_b2, Wx_w3);
    node_out_kernel<<<nsm, 512, NODE_SMEM_BYTES>>>(h, x, Wh_w1, Wh_b1, Wh_w2, Wh_b2, out);
}